// round 3
// baseline (speedup 1.0000x reference)
#include <cuda_runtime.h>
#include <math.h>

#define NN 50000
#define MAXE 1700000
#define BN_EPS 1e-5f
#define L2_EPS 1e-12f

// ---------------- scratch (static device globals; no allocation) ----------------
__device__ float g_dinv[NN];                       // degree -> rsqrt(degree)
__device__ __align__(16) float g_t[NN * 64];       // t = h @ W (pre-aggregation), also encoder temp
__device__ __align__(16) float g_agg[NN * 64];     // aggregation accumulator
__device__ __align__(16) float g_h[NN * 64];       // current node features
__device__ int   g_src[MAXE];
__device__ int   g_dst[MAXE];
__device__ float g_coef[MAXE];                     // dinv[src]*dinv[dst]
__device__ float g_stats[128];                     // [0:64) sum, [64:128) sumsq
__device__ float g_a[64];                          // BN fold: y = x*a + c
__device__ float g_c[64];
__device__ int   g_not64;                          // 1 if edge_index is int32 layout

// ---------------- edge_index dtype detection ----------------
// int64 little-endian values < 2^31 have all odd 32-bit words == 0.
// int32 data has random node ids at odd words. Reads stay within the first
// 2*ne int32 words (valid under both interpretations).
__global__ void detect_kernel(const int* __restrict__ w, int ne) {
    int i = threadIdx.x;                 // 256 threads, check odd words 1..2047
    int nz = 0;
    for (int k = 2 * i + 1; k < 2048 && k < 2 * ne; k += 512)
        nz |= (w[k] != 0);
    if (nz) atomicExch(&g_not64, 1);
}

__global__ void zero_flag_kernel() { if (threadIdx.x == 0) g_not64 = 0; }

// ---------------- small utility kernels ----------------
__global__ void set_deg_kernel() {
    int i = blockIdx.x * blockDim.x + threadIdx.x;
    if (i < NN) g_dinv[i] = 1.0f;   // self-loop
}

// decode src/dst per layout, store int32 copies, accumulate degree(dst)
__global__ void deg_prep_kernel(const int* __restrict__ w, int ne) {
    int e = blockIdx.x * blockDim.x + threadIdx.x;
    if (e >= ne) return;
    int s, d;
    if (g_not64) {              // int32: [src[ne], dst[ne]]
        s = w[e];
        d = w[ne + e];
    } else {                    // int64: low words at even positions
        s = w[2 * e];
        d = w[2 * (ne + e)];
    }
    g_src[e] = s;
    g_dst[e] = d;
    atomicAdd(&g_dinv[d], 1.0f);
}

__global__ void dinv_kernel() {
    int i = blockIdx.x * blockDim.x + threadIdx.x;
    if (i < NN) g_dinv[i] = rsqrtf(g_dinv[i]);
}

__global__ void coef_kernel(int ne) {
    int e = blockIdx.x * blockDim.x + threadIdx.x;
    if (e < ne) g_coef[e] = g_dinv[g_src[e]] * g_dinv[g_dst[e]];
}

__global__ void zero_stats_kernel() {
    int i = threadIdx.x;
    if (i < 128) g_stats[i] = 0.0f;
}

// ---------------- GEMM:  out[row, :] = in[row, :K] @ W[K, NOUT]  ----------------
// EPI: 0 = +bias, plain store  |  1 = +bias, relu store  |  2 = store t AND agg = t*dinv^2 + bias
// INAFF: apply per-column affine (g_a, g_c) to the input while loading (folds BN)
template<int K, int NOUT, int EPI, bool INAFF>
__global__ void __launch_bounds__(128)
gemm_kernel(const float* __restrict__ in, const float* __restrict__ W,
            const float* __restrict__ bias, float* __restrict__ out,
            float* __restrict__ agg, int n)
{
    __shared__ float Ws[K * NOUT];
    __shared__ float bs[NOUT];
    __shared__ float as_[64], cs_[64];

    for (int i = threadIdx.x; i < K * NOUT; i += blockDim.x) Ws[i] = W[i];
    if (threadIdx.x < NOUT) bs[threadIdx.x] = bias[threadIdx.x];
    if (INAFF && threadIdx.x < K) {
        as_[threadIdx.x] = g_a[threadIdx.x];
        cs_[threadIdx.x] = g_c[threadIdx.x];
    }
    __syncthreads();

    int row = blockIdx.x * blockDim.x + threadIdx.x;
    if (row >= n) return;

    const float4* xr4 = (const float4*)(in + (long long)row * K);

    float acc[NOUT];
#pragma unroll
    for (int j = 0; j < NOUT; j++) acc[j] = (EPI == 2) ? 0.0f : bs[j];

#pragma unroll
    for (int kk = 0; kk < K; kk += 16) {
        float4 xv0 = xr4[kk / 4 + 0];
        float4 xv1 = xr4[kk / 4 + 1];
        float4 xv2 = xr4[kk / 4 + 2];
        float4 xv3 = xr4[kk / 4 + 3];
        float xs[16] = {xv0.x, xv0.y, xv0.z, xv0.w,
                        xv1.x, xv1.y, xv1.z, xv1.w,
                        xv2.x, xv2.y, xv2.z, xv2.w,
                        xv3.x, xv3.y, xv3.z, xv3.w};
        if (INAFF) {
#pragma unroll
            for (int i = 0; i < 16; i++)
                xs[i] = fmaf(xs[i], as_[kk + i], cs_[kk + i]);
        }
#pragma unroll
        for (int i = 0; i < 16; i++) {
            float xk = xs[i];
            const float* wr = Ws + (kk + i) * NOUT;
#pragma unroll
            for (int j = 0; j < NOUT; j += 4) {
                float4 w = *(const float4*)(wr + j);
                acc[j + 0] = fmaf(xk, w.x, acc[j + 0]);
                acc[j + 1] = fmaf(xk, w.y, acc[j + 1]);
                acc[j + 2] = fmaf(xk, w.z, acc[j + 2]);
                acc[j + 3] = fmaf(xk, w.w, acc[j + 3]);
            }
        }
    }

    if (EPI == 2) {
        float dv = g_dinv[row];
        float d2 = dv * dv;
        float4* o4 = (float4*)(out + (long long)row * NOUT);
        float4* a4 = (float4*)(agg + (long long)row * NOUT);
#pragma unroll
        for (int j = 0; j < NOUT; j += 4) {
            float4 t = make_float4(acc[j], acc[j + 1], acc[j + 2], acc[j + 3]);
            o4[j / 4] = t;
            float4 a = make_float4(fmaf(t.x, d2, bs[j + 0]),
                                   fmaf(t.y, d2, bs[j + 1]),
                                   fmaf(t.z, d2, bs[j + 2]),
                                   fmaf(t.w, d2, bs[j + 3]));
            a4[j / 4] = a;
        }
    } else {
        float4* o4 = (float4*)(out + (long long)row * NOUT);
#pragma unroll
        for (int j = 0; j < NOUT; j += 4) {
            float4 v = make_float4(acc[j], acc[j + 1], acc[j + 2], acc[j + 3]);
            if (EPI == 1) {
                v.x = fmaxf(v.x, 0.0f); v.y = fmaxf(v.y, 0.0f);
                v.z = fmaxf(v.z, 0.0f); v.w = fmaxf(v.w, 0.0f);
            }
            o4[j / 4] = v;
        }
    }
}

// ---------------- edge scatter: agg[dst] += t[src] * coef ----------------
template<int C>
__global__ void __launch_bounds__(256)
scatter_kernel(int ne)
{
    const int VPE = C / 4;                 // float4s per edge (16 or 8)
    int gid = blockIdx.x * blockDim.x + threadIdx.x;
    int total = ne * VPE;
    if (gid >= total) return;
    int e, j;
    if (C == 64) { e = gid >> 4; j = gid & 15; }
    else         { e = gid >> 3; j = gid & 7; }

    int s = g_src[e];
    int d = g_dst[e];
    float cf = g_coef[e];

    float4 v = *((const float4*)g_t + (long long)s * VPE + j);
    v.x *= cf; v.y *= cf; v.z *= cf; v.w *= cf;

    float4* ap = (float4*)(g_agg + (long long)d * C + j * 4);
    atomicAdd(ap, v);   // vector red, sm_90+
}

// ---------------- BN statistics (column sum / sumsq) ----------------
template<int C>
__global__ void __launch_bounds__(256)
bnstats_kernel(const float* __restrict__ x, int n)
{
    const int BLK = 256;
    const int GR = BLK / C;                // row-groups per block
    int col = threadIdx.x & (C - 1);
    int grp = threadIdx.x / C;

    float s = 0.0f, s2 = 0.0f;
    for (int r = blockIdx.x * GR + grp; r < n; r += gridDim.x * GR) {
        float v = x[(long long)r * C + col];
        s += v;
        s2 = fmaf(v, v, s2);
    }
    __shared__ float sh0[BLK], sh1[BLK];
    sh0[threadIdx.x] = s;
    sh1[threadIdx.x] = s2;
    __syncthreads();
    if (grp == 0) {
#pragma unroll
        for (int g = 1; g < GR; g++) {
            s  += sh0[g * C + col];
            s2 += sh1[g * C + col];
        }
        atomicAdd(&g_stats[col], s);
        atomicAdd(&g_stats[64 + col], s2);
    }
}

template<int C>
__global__ void bnparams_kernel(const float* __restrict__ gamma,
                                const float* __restrict__ beta, float inv_n)
{
    int t = threadIdx.x;
    if (t < C) {
        float s = g_stats[t], s2 = g_stats[64 + t];
        float mu = s * inv_n;
        float var = fmaxf(s2 * inv_n - mu * mu, 0.0f);
        float rstd = rsqrtf(var + BN_EPS);
        float a = rstd * gamma[t];
        g_a[t] = a;
        g_c[t] = fmaf(-mu, a, beta[t]);
    }
}

// BN apply + relu (conv layers 1 & 2)
template<int C>
__global__ void __launch_bounds__(256)
bnapply_relu_kernel(const float* __restrict__ in, float* __restrict__ out, int n)
{
    int i = blockIdx.x * blockDim.x + threadIdx.x;
    if (i >= n * (C / 4)) return;
    float4 v = ((const float4*)in)[i];
    int c0 = (i & (C / 4 - 1)) * 4;
    v.x = fmaxf(fmaf(v.x, g_a[c0 + 0], g_c[c0 + 0]), 0.0f);
    v.y = fmaxf(fmaf(v.y, g_a[c0 + 1], g_c[c0 + 1]), 0.0f);
    v.z = fmaxf(fmaf(v.z, g_a[c0 + 2], g_c[c0 + 2]), 0.0f);
    v.w = fmaxf(fmaf(v.w, g_a[c0 + 3], g_c[c0 + 3]), 0.0f);
    ((float4*)out)[i] = v;
}

// Final: BN (32 cols) + row L2 normalize. Warp per row (lane == column).
__global__ void __launch_bounds__(256)
final_kernel(float* __restrict__ out, int n)
{
    int t = blockIdx.x * blockDim.x + threadIdx.x;
    int row = t >> 5, lane = t & 31;
    if (row >= n) return;
    float v = fmaf(g_agg[(long long)row * 32 + lane], g_a[lane], g_c[lane]);
    float ss = v * v;
#pragma unroll
    for (int o = 16; o; o >>= 1) ss += __shfl_xor_sync(0xFFFFFFFFu, ss, o);
    out[(long long)row * 32 + lane] = v / fmaxf(sqrtf(ss), L2_EPS);
}

// ---------------- launch ----------------
extern "C" void kernel_launch(void* const* d_in, const int* in_sizes, int n_in,
                              void* d_out, int out_size)
{
    const float* x  = (const float*)d_in[0];
    const int*   ew = (const int*)d_in[1];       // edge_index words (int32 or int64 layout)
    const float* ne_w1 = (const float*)d_in[2];
    const float* ne_b1 = (const float*)d_in[3];
    const float* ne_g  = (const float*)d_in[4];
    const float* ne_be = (const float*)d_in[5];
    const float* ne_w2 = (const float*)d_in[6];
    const float* ne_b2 = (const float*)d_in[7];
    const float* c1_w = (const float*)d_in[8];
    const float* c1_b = (const float*)d_in[9];
    const float* g1   = (const float*)d_in[10];
    const float* be1  = (const float*)d_in[11];
    const float* c2_w = (const float*)d_in[12];
    const float* c2_b = (const float*)d_in[13];
    const float* g2   = (const float*)d_in[14];
    const float* be2  = (const float*)d_in[15];
    const float* c3_w = (const float*)d_in[16];
    const float* c3_b = (const float*)d_in[17];
    const float* g3   = (const float*)d_in[18];
    const float* be3  = (const float*)d_in[19];
    float* out = (float*)d_out;

    int ne = in_sizes[1] / 2;
    if (ne > MAXE) ne = MAXE;

    const float inv_n = 1.0f / (float)NN;
    const int NB = (NN + 255) / 256;
    const int EB = (ne + 255) / 256;

    float* dT;   cudaGetSymbolAddress((void**)&dT,   g_t);
    float* dAgg; cudaGetSymbolAddress((void**)&dAgg, g_agg);
    float* dH;   cudaGetSymbolAddress((void**)&dH,   g_h);

    // edge dtype detection + degrees + edge prep
    zero_flag_kernel<<<1, 32>>>();
    detect_kernel<<<1, 256>>>(ew, ne);
    set_deg_kernel<<<NB, 256>>>();
    deg_prep_kernel<<<EB, 256>>>(ew, ne);
    dinv_kernel<<<NB, 256>>>();
    coef_kernel<<<EB, 256>>>(ne);

    const int GB = (NN + 127) / 128;   // gemm blocks (128 threads)

    // ---- node encoder: relu(x@W1+b1) -> BN (folded into next GEMM) -> @W2+b2
    gemm_kernel<32, 64, 1, false><<<GB, 128>>>(x, ne_w1, ne_b1, dT, nullptr, NN);
    zero_stats_kernel<<<1, 128>>>();
    bnstats_kernel<64><<<256, 256>>>(dT, NN);
    bnparams_kernel<64><<<1, 64>>>(ne_g, ne_be, inv_n);
    gemm_kernel<64, 64, 0, true><<<GB, 128>>>(dT, ne_w2, ne_b2, dH, nullptr, NN);

    // ---- conv layer 1 (H=64, relu)
    gemm_kernel<64, 64, 2, false><<<GB, 128>>>(dH, c1_w, c1_b, dT, dAgg, NN);
    scatter_kernel<64><<<(ne * 16 + 255) / 256, 256>>>(ne);
    zero_stats_kernel<<<1, 128>>>();
    bnstats_kernel<64><<<256, 256>>>(dAgg, NN);
    bnparams_kernel<64><<<1, 64>>>(g1, be1, inv_n);
    bnapply_relu_kernel<64><<<(NN * 16 + 255) / 256, 256>>>(dAgg, dH, NN);

    // ---- conv layer 2 (H=64, relu)
    gemm_kernel<64, 64, 2, false><<<GB, 128>>>(dH, c2_w, c2_b, dT, dAgg, NN);
    scatter_kernel<64><<<(ne * 16 + 255) / 256, 256>>>(ne);
    zero_stats_kernel<<<1, 128>>>();
    bnstats_kernel<64><<<256, 256>>>(dAgg, NN);
    bnparams_kernel<64><<<1, 64>>>(g2, be2, inv_n);
    bnapply_relu_kernel<64><<<(NN * 16 + 255) / 256, 256>>>(dAgg, dH, NN);

    // ---- conv layer 3 (out=32) + BN + L2 normalize
    gemm_kernel<64, 32, 2, false><<<GB, 128>>>(dH, c3_w, c3_b, dT, dAgg, NN);
    scatter_kernel<32><<<(ne * 8 + 255) / 256, 256>>>(ne);
    zero_stats_kernel<<<1, 128>>>();
    bnstats_kernel<32><<<256, 256>>>(dAgg, NN);
    bnparams_kernel<32><<<1, 32>>>(g3, be3, inv_n);
    final_kernel<<<(NN * 32 + 255) / 256, 256>>>(out, NN);
}